// round 13
// baseline (speedup 1.0000x reference)
#include <cuda_runtime.h>
#include <cuda_bf16.h>
#include <math.h>
#include <stdint.h>

#define E_   8
#define B_   16384
#define D_   384
#define R_   32

#define BM 128
#define BN 128

// ---------------------------------------------------------------------------
// Static scratch (~77 MB total)
// ---------------------------------------------------------------------------
__device__ double                       g_err2[3 * E_ * B_];          // 3 MB
__device__ float                        g_newre[E_ * B_ * R_];        // 17 MB
__device__ __align__(16) __nv_bfloat16  g_xsp[3][B_ * D_];            // 37.7 MB (full B)
__device__ __align__(16) __nv_bfloat16  g_asp[3][E_ * D_ * D_];       // 7.1 MB ([e][f][d])
__device__ __align__(16) __nv_bfloat16  g_asp2[3][E_ * D_ * D_];      // 7.1 MB ([e][d][f])
__device__ __align__(16) __nv_bfloat16  g_wsp[3][E_ * 128 * D_];      // 2.4 MB ([e][n][f])
__device__ __align__(16) __nv_bfloat16  g_msp[3][E_ * 128 * D_];      // 2.4 MB (M^T: [e][n][d])

// ---------------------------------------------------------------------------
// k0a: split A_align into BOTH orientations (once).
// g_asp  [s][e][f][d]  (B-operand for x_al tiles)
// g_asp2 [s][e][d][f]  (B-operand for M = A @ Wc^T)
// ---------------------------------------------------------------------------
__global__ __launch_bounds__(256)
void k0a_split(const float* __restrict__ A)
{
    int idx = blockIdx.x * 256 + threadIdx.x;           // over E*384*96
    if (idx >= E_ * D_ * (D_ / 4)) return;
    int e  = idx / (D_ * (D_ / 4));
    int r  = idx % (D_ * (D_ / 4));
    int k  = r / (D_ / 4);                              // d index
    int n4 = (r % (D_ / 4)) * 4;                        // f index base
    float4 v = *reinterpret_cast<const float4*>(A + ((size_t)e * D_ + k) * D_ + n4);
    const float vv[4] = {v.x, v.y, v.z, v.w};
#pragma unroll
    for (int i = 0; i < 4; i++) {
        float f = vv[i];
        __nv_bfloat16 h1 = __float2bfloat16(f);
        float r1 = f - __bfloat162float(h1);
        __nv_bfloat16 h2 = __float2bfloat16(r1);
        float r2 = r1 - __bfloat162float(h2);
        __nv_bfloat16 h3 = __float2bfloat16(r2);
        size_t o1 = ((size_t)e * D_ + (n4 + i)) * D_ + k;   // [f][d]
        size_t o2 = ((size_t)e * D_ + k) * D_ + (n4 + i);   // [d][f]
        g_asp[0][o1] = h1; g_asp[1][o1] = h2; g_asp[2][o1] = h3;
        g_asp2[0][o2] = h1; g_asp2[1][o2] = h2; g_asp2[2][o2] = h3;
    }
}

// ---------------------------------------------------------------------------
// k0x: split x (full B) -> g_xsp[s][b][d] (bf16).
// ---------------------------------------------------------------------------
__global__ __launch_bounds__(256)
void k0x_split(const float* __restrict__ x)
{
    int idx = blockIdx.x * 256 + threadIdx.x;           // over B*96
    if (idx >= B_ * (D_ / 4)) return;
    int b  = idx / (D_ / 4);
    int k4 = (idx % (D_ / 4)) * 4;
    float4 v = *reinterpret_cast<const float4*>(x + (size_t)b * D_ + k4);
    const float vv[4] = {v.x, v.y, v.z, v.w};
    __nv_bfloat16 o1[4], o2[4], o3[4];
#pragma unroll
    for (int i = 0; i < 4; i++) {
        float f = vv[i];
        __nv_bfloat16 h1 = __float2bfloat16(f);
        float r1 = f - __bfloat162float(h1);
        __nv_bfloat16 h2 = __float2bfloat16(r1);
        float r2 = r1 - __bfloat162float(h2);
        o1[i] = h1; o2[i] = h2; o3[i] = __float2bfloat16(r2);
    }
    size_t o = (size_t)b * D_ + k4;
    *reinterpret_cast<uint64_t*>(&g_xsp[0][o]) = *reinterpret_cast<uint64_t*>(o1);
    *reinterpret_cast<uint64_t*>(&g_xsp[1][o]) = *reinterpret_cast<uint64_t*>(o2);
    *reinterpret_cast<uint64_t*>(&g_xsp[2][o]) = *reinterpret_cast<uint64_t*>(o3);
}

// ---------------------------------------------------------------------------
// k0w: split combined weight block [gate|x_val|dt|phase] -> g_wsp[s][e][n][f].
// ---------------------------------------------------------------------------
__global__ __launch_bounds__(256)
void k0w_split(const float* __restrict__ Win, const float* __restrict__ Wdt,
               const float* __restrict__ Wph)
{
    int idx = blockIdx.x * 256 + threadIdx.x;           // over E*128*96
    if (idx >= E_ * 128 * (D_ / 4)) return;
    int e  = idx / (128 * (D_ / 4));
    int r  = idx % (128 * (D_ / 4));
    int n  = r / (D_ / 4);
    int k4 = (r % (D_ / 4)) * 4;
    const float* src;
    if (n < 64)      src = Win + ((size_t)e * (4 * R_) + n) * D_;
    else if (n < 96) src = Wdt + ((size_t)e * R_ + (n - 64)) * D_;
    else             src = Wph + ((size_t)e * R_ + (n - 96)) * D_;
    float4 v = *reinterpret_cast<const float4*>(src + k4);
    const float vv[4] = {v.x, v.y, v.z, v.w};
#pragma unroll
    for (int i = 0; i < 4; i++) {
        float f = vv[i];
        __nv_bfloat16 h1 = __float2bfloat16(f);
        float r1 = f - __bfloat162float(h1);
        __nv_bfloat16 h2 = __float2bfloat16(r1);
        float r2 = r1 - __bfloat162float(h2);
        __nv_bfloat16 h3 = __float2bfloat16(r2);
        size_t o = ((size_t)e * 128 + n) * D_ + k4 + i;
        g_wsp[0][o] = h1; g_wsp[1][o] = h2; g_wsp[2][o] = h3;
    }
}

// ---------------------------------------------------------------------------
// mma.sync / ldmatrix / cp.async helpers (baseline PTX, no 'a' features)
// ---------------------------------------------------------------------------
__device__ __forceinline__ uint32_t smem_u32(const void* p) {
    uint32_t a;
    asm("{ .reg .u64 t; cvta.to.shared.u64 t, %1; cvt.u32.u64 %0, t; }" : "=r"(a) : "l"(p));
    return a;
}
__device__ __forceinline__ void ldsm_x4(uint32_t* r, uint32_t a) {
    asm volatile("ldmatrix.sync.aligned.m8n8.x4.shared.b16 {%0,%1,%2,%3}, [%4];"
                 : "=r"(r[0]), "=r"(r[1]), "=r"(r[2]), "=r"(r[3]) : "r"(a));
}
__device__ __forceinline__ void mma_bf16(float* c, const uint32_t* a, uint32_t b0, uint32_t b1) {
    asm volatile("mma.sync.aligned.m16n8k16.row.col.f32.bf16.bf16.f32 "
                 "{%0,%1,%2,%3}, {%4,%5,%6,%7}, {%8,%9}, {%0,%1,%2,%3};"
                 : "+f"(c[0]), "+f"(c[1]), "+f"(c[2]), "+f"(c[3])
                 : "r"(a[0]), "r"(a[1]), "r"(a[2]), "r"(a[3]), "r"(b0), "r"(b1));
}
__device__ __forceinline__ void cp_async16(uint32_t dst, const void* src) {
    asm volatile("cp.async.cg.shared.global [%0], [%1], 16;"
                 :: "r"(dst), "l"(__cvta_generic_to_global(src)) : "memory");
}
#define CP_COMMIT()  asm volatile("cp.async.commit_group;" ::: "memory")
#define CP_WAIT(n)   asm volatile("cp.async.wait_group %0;" :: "n"(n) : "memory")

#define KC       64
#define TILE_B2  16384                 // 128 rows * 128 bytes
#define STAGE_B  (6 * TILE_B2)         // 98304: [op(2)][split(3)] tiles
#define SM_PD    (2 * STAGE_B)         // 196608
#define SM_TOT   (SM_PD + 1024)        // 197632

#define NT_GEMM  512                   // 16 warps: 4 m-groups x 4 n-groups

__device__ __forceinline__ float softplus_f(float z) {
    return fmaxf(z, 0.f) + log1pf(expf(-fabsf(z)));
}

// Shared mainloop body (16-warp version, warp tile 32x32).
#define MAINLOOP_CHUNK(stage)                                                   \
    _Pragma("unroll")                                                           \
    for (int ks = 0; ks < 4; ks++) {                                            \
        const uint32_t kb = (uint32_t)(ks * 32);                                \
        uint32_t xf[3][2][4];                                                   \
        _Pragma("unroll")                                                       \
        for (int s = 0; s < 3; s++)                                             \
            _Pragma("unroll")                                                   \
            for (int mi = 0; mi < 2; mi++) {                                    \
                int r_ = xrow + mi * 16;                                        \
                ldsm_x4(xf[s][mi], (stage) + s * TILE_B2 + r_ * 128             \
                                  + ((kb + xk0) ^ (uint32_t)((r_ & 7) << 4)));  \
            }                                                                   \
        uint32_t bfb[2][2][4];                                                  \
        _Pragma("unroll")                                                       \
        for (int t = 0; t < 2; t++) {                                           \
            int r_ = brow + t * 16;                                             \
            ldsm_x4(bfb[0][t], (stage) + 3 * TILE_B2 + r_ * 128                 \
                              + ((kb + bk0) ^ (uint32_t)((r_ & 7) << 4)));      \
        }                                                                       \
        _Pragma("unroll")                                                       \
        for (int sa = 0; sa < 3; sa++) {                                        \
            const int cur = sa & 1;                                             \
            if (sa < 2) {                                                       \
                _Pragma("unroll")                                               \
                for (int t = 0; t < 2; t++) {                                   \
                    int r_ = brow + t * 16;                                     \
                    ldsm_x4(bfb[cur ^ 1][t],                                    \
                            (stage) + (4 + sa) * TILE_B2 + r_ * 128             \
                            + ((kb + bk0) ^ (uint32_t)((r_ & 7) << 4)));        \
                }                                                               \
            }                                                                   \
            const int nsx = (sa == 0) ? 3 : (sa == 1) ? 2 : 1;                  \
            _Pragma("unroll")                                                   \
            for (int sx = 0; sx < 3; sx++) {                                    \
                if (sx < nsx) {                                                 \
                    _Pragma("unroll")                                           \
                    for (int mi = 0; mi < 2; mi++)                              \
                        _Pragma("unroll")                                       \
                        for (int ni = 0; ni < 4; ni++)                          \
                            mma_bf16(acc[mi][ni], xf[sx][mi],                   \
                                     bfb[cur][ni >> 1][(ni & 1) * 2],           \
                                     bfb[cur][ni >> 1][(ni & 1) * 2 + 1]);      \
                }                                                               \
            }                                                                   \
        }                                                                       \
    }

// 3-way bf16 split of a float pair, stored to g_msp-style arrays.
__device__ __forceinline__ void split_store_pair(
    __nv_bfloat16* p0, __nv_bfloat16* p1, __nv_bfloat16* p2,
    size_t oi, float c0, float c1)
{
    __nv_bfloat16 a1 = __float2bfloat16(c0);
    float q0 = c0 - __bfloat162float(a1);
    __nv_bfloat16 a2 = __float2bfloat16(q0);
    q0 -= __bfloat162float(a2);
    __nv_bfloat16 a3 = __float2bfloat16(q0);
    __nv_bfloat16 b1 = __float2bfloat16(c1);
    float q1 = c1 - __bfloat162float(b1);
    __nv_bfloat16 b2 = __float2bfloat16(q1);
    q1 -= __bfloat162float(b2);
    __nv_bfloat16 b3 = __float2bfloat16(q1);
    __nv_bfloat162 p;
    p.x = a1; p.y = b1; *reinterpret_cast<__nv_bfloat162*>(p0 + oi) = p;
    p.x = a2; p.y = b2; *reinterpret_cast<__nv_bfloat162*>(p1 + oi) = p;
    p.x = a3; p.y = b3; *reinterpret_cast<__nv_bfloat162*>(p2 + oi) = p;
}

// ---------------------------------------------------------------------------
// kM: M^T[e][n][d] = Wc[e] @ A[e]  (rows n=128, cols d per tile, K=f=384),
// output split 3-way bf16 to g_msp. Grid (3, 8), 512 threads.
// ---------------------------------------------------------------------------
__global__ __launch_bounds__(NT_GEMM, 1)
void km_mma()
{
    extern __shared__ char smem[];
    const uint32_t sb = smem_u32(smem);
    const int tid = threadIdx.x;
    const int wid = tid >> 5;
    const int l   = tid & 31;

    const int dt = blockIdx.x;   // 0..2 (d tile)
    const int e  = blockIdx.y;   // 0..7

    const int warp_m = (wid & 3) * 32;
    const int warp_n = (wid >> 2) * 32;

    const int      xrow = warp_m + (l & 15);
    const uint32_t xk0  = (uint32_t)((l >> 4) * 16);
    const int      brow = warp_n + ((l >> 4) << 3) + (l & 7);
    const uint32_t bk0  = (uint32_t)(((l >> 3) & 1) * 16);

    float acc[2][4][4] = {};

    auto issue = [&](int c) {
        const int buf = c & 1;
        const int k0  = c * KC;
#pragma unroll
        for (int it = 0; it < 12; it++) {
            int lin  = tid + it * NT_GEMM;
            int tile = lin >> 10;
            int u    = lin & 1023;
            int m    = u >> 3;
            int kk8  = (u & 7) * 8;
            const __nv_bfloat16* src;
            if (tile < 3)
                src = &g_wsp[tile][((size_t)e * 128 + m) * D_ + k0 + kk8];
            else
                src = &g_asp2[tile - 3][((size_t)e * D_ + dt * 128 + m) * D_ + k0 + kk8];
            uint32_t boff = (uint32_t)(m * 128 + kk8 * 2);
            uint32_t dst  = sb + buf * STAGE_B + tile * TILE_B2
                          + (boff ^ ((boff >> 3) & 0x70));
            cp_async16(dst, src);
        }
        CP_COMMIT();
    };

    issue(0);
    for (int c = 0; c < 6; c++) {
        if (c < 5) { issue(c + 1); CP_WAIT(1); }
        else       { CP_WAIT(0); }
        __syncthreads();
        const uint32_t stage = sb + (uint32_t)((c & 1) * STAGE_B);
        MAINLOOP_CHUNK(stage)
        __syncthreads();
    }

    // epilogue: split-store M^T rows (n) x cols (d tile)
    const int cb = (l & 3) * 2;
#pragma unroll
    for (int mi = 0; mi < 2; mi++)
#pragma unroll
        for (int h = 0; h < 2; h++) {
            const int rl = warp_m + mi * 16 + (l >> 2) + h * 8;       // n
            const size_t base = ((size_t)e * 128 + rl) * D_ + dt * 128 + warp_n;
#pragma unroll
            for (int ni = 0; ni < 4; ni++)
                split_store_pair(g_msp[0], g_msp[1], g_msp[2],
                                 base + ni * 8 + cb,
                                 acc[mi][ni][h * 2], acc[mi][ni][h * 2 + 1]);
        }
}

// ---------------------------------------------------------------------------
// kG (grand GEMM): grid (4, B/128, 8), 512 threads.
//   nt<3 : x_al tile = x @ A[e]^T  -> fp64 err^2 partials only
//   nt==3: proj = x @ M[e]        -> transcendental epilogue -> g_newre
// ---------------------------------------------------------------------------
__global__ __launch_bounds__(NT_GEMM, 1)
void kg_mma(const float* __restrict__ x,
            const float* __restrict__ sre, const float* __restrict__ sim,
            const float* __restrict__ lom, const float* __restrict__ ltm,
            const float* __restrict__ nuv)
{
    extern __shared__ char smem[];
    __shared__ float ph_sh[R_], ex_sh[R_];
    const uint32_t sb = smem_u32(smem);
    const int tid = threadIdx.x;
    const int wid = tid >> 5;
    const int l   = tid & 31;

    const int nt = blockIdx.x;   // 0..2: err tiles; 3: proj tile
    const int bt = blockIdx.y;   // 0..127
    const int e  = blockIdx.z;   // 0..7

    double* pd = reinterpret_cast<double*>(smem + SM_PD);
    if (nt < 3) {
        if (tid < 128) pd[tid] = 0.0;
    } else {
        if (tid < R_) {
            ph_sh[tid] = expf(lom[e * R_ + tid]) / (expf(ltm[e * R_ + tid]) + 1e-6f);
            ex_sh[tid] = expf(nuv[e * R_ + tid]);
        }
    }

    const int warp_m = (wid & 3) * 32;
    const int warp_n = (wid >> 2) * 32;

    const int      xrow = warp_m + (l & 15);
    const uint32_t xk0  = (uint32_t)((l >> 4) * 16);
    const int      brow = warp_n + ((l >> 4) << 3) + (l & 7);
    const uint32_t bk0  = (uint32_t)(((l >> 3) & 1) * 16);

    float acc[2][4][4] = {};

    auto issue = [&](int c) {
        const int buf = c & 1;
        const int k0  = c * KC;
#pragma unroll
        for (int it = 0; it < 12; it++) {
            int lin  = tid + it * NT_GEMM;
            int tile = lin >> 10;
            int u    = lin & 1023;
            int m    = u >> 3;
            int kk8  = (u & 7) * 8;
            const __nv_bfloat16* src;
            if (tile < 3)
                src = &g_xsp[tile][((size_t)(bt * BM + m)) * D_ + k0 + kk8];
            else if (nt < 3)
                src = &g_asp[tile - 3][((size_t)e * D_ + (nt * BN + m)) * D_ + k0 + kk8];
            else
                src = &g_msp[tile - 3][((size_t)e * 128 + m) * D_ + k0 + kk8];
            uint32_t boff = (uint32_t)(m * 128 + kk8 * 2);
            uint32_t dst  = sb + buf * STAGE_B + tile * TILE_B2
                          + (boff ^ ((boff >> 3) & 0x70));
            cp_async16(dst, src);
        }
        CP_COMMIT();
    };

    issue(0);
    for (int c = 0; c < 6; c++) {
        if (c < 5) { issue(c + 1); CP_WAIT(1); }
        else       { CP_WAIT(0); }
        __syncthreads();
        const uint32_t stage = sb + (uint32_t)((c & 1) * STAGE_B);
        MAINLOOP_CHUNK(stage)
        __syncthreads();
    }

    const int cb = (l & 3) * 2;
    if (nt < 3) {
        // ---- err^2 epilogue (fp64 partials only; no x_al store) ----
        double es[2][2] = {{0.0, 0.0}, {0.0, 0.0}};
#pragma unroll
        for (int mi = 0; mi < 2; mi++)
#pragma unroll
            for (int h = 0; h < 2; h++) {
                const int rl   = warp_m + mi * 16 + (l >> 2) + h * 8;
                const int grow = bt * BM + rl;
                const float* xp = x + (size_t)grow * D_ + nt * BN + warp_n;
                double s = 0.0;
#pragma unroll
                for (int ni = 0; ni < 4; ni++) {
                    float2 xv = *reinterpret_cast<const float2*>(xp + ni * 8 + cb);
                    float d0 = xv.x - acc[mi][ni][h * 2 + 0];
                    float d1 = xv.y - acc[mi][ni][h * 2 + 1];
                    s += (double)d0 * d0 + (double)d1 * d1;
                }
                es[mi][h] = s;
            }
#pragma unroll
        for (int mi = 0; mi < 2; mi++)
#pragma unroll
            for (int h = 0; h < 2; h++) {
                double s = es[mi][h];
                s += __shfl_xor_sync(0xFFFFFFFFu, s, 1);
                s += __shfl_xor_sync(0xFFFFFFFFu, s, 2);
                if ((l & 3) == 0)
                    atomicAdd(&pd[warp_m + mi * 16 + (l >> 2) + h * 8], s);
            }
        __syncthreads();
        if (tid < 128)
            g_err2[(size_t)nt * (E_ * B_) + (size_t)e * B_ + (size_t)(bt * BM + tid)]
                = pd[tid];
    } else {
        // ---- proj epilogue: stage to smem, transcendentals -> g_newre ----
        float* S = reinterpret_cast<float*>(smem);
#pragma unroll
        for (int mi = 0; mi < 2; mi++)
#pragma unroll
            for (int h = 0; h < 2; h++) {
                const int rl = warp_m + mi * 16 + (l >> 2) + h * 8;
#pragma unroll
                for (int ni = 0; ni < 4; ni++)
                    *reinterpret_cast<float2*>(&S[rl * 132 + warp_n + ni * 8 + cb]) =
                        make_float2(acc[mi][ni][h * 2], acc[mi][ni][h * 2 + 1]);
            }
        __syncthreads();
        const int row = tid >> 2;
        const int rh  = (tid & 3) * 8;
        const int b   = bt * BM + row;
        const float* srp = sre + ((size_t)e * B_ + b) * R_ + rh;
        const float* sip = sim + ((size_t)e * B_ + b) * R_ + rh;
        float* nrp = g_newre + ((size_t)e * B_ + b) * R_ + rh;
        const float PIf = 3.14159265358979323846f;
#pragma unroll
        for (int j = 0; j < 8; j++) {
            const int r = rh + j;
            float gate = S[row * 132 + r];
            float xval = S[row * 132 + 32 + r];
            float dtp  = S[row * 132 + 64 + r];
            float phv  = S[row * 132 + 96 + r];
            float dtv   = softplus_f(dtp);
            float phase = tanhf(phv) * PIf;
            float angle = dtv * (ph_sh[r] + phase);
            float dec   = expf(-dtv * ex_sh[r]);
            float sv, cv;
            sincosf(angle, &sv, &cv);
            float sig = 1.f / (1.f + expf(-gate));
            nrp[j] = (srp[j] * cv - sip[j] * sv) * dec + sig * xval;
        }
    }
}

// ---------------------------------------------------------------------------
// K3: per-row winner (argmin err^2) + out = new_re @ W_out^T   (unchanged)
// ---------------------------------------------------------------------------
__global__ __launch_bounds__(128)
void k3_out(const float* __restrict__ Wout, float* __restrict__ out)
{
    const int gwarp = (blockIdx.x * blockDim.x + threadIdx.x) >> 5;
    const int lane = threadIdx.x & 31;
    if (gwarp >= B_) return;
    const int b = gwarp;

    double v = 1.0e300;
    if (lane < E_) {
        const size_t idx = (size_t)lane * B_ + b;
        v = g_err2[idx] + g_err2[(size_t)(E_ * B_) + idx] + g_err2[2 * (size_t)(E_ * B_) + idx];
    }
    int w = lane;
#pragma unroll
    for (int ofs = 1; ofs < 8; ofs <<= 1) {
        double ov = __shfl_xor_sync(0xFFFFFFFFu, v, ofs);
        int    ow = __shfl_xor_sync(0xFFFFFFFFu, w, ofs);
        if (ov < v || (ov == v && ow < w)) { v = ov; w = ow; }
    }
    w = __shfl_sync(0xFFFFFFFFu, w, 0);

    __shared__ float nr_sh[4][R_];
    const int wslot = threadIdx.x >> 5;
    nr_sh[wslot][lane] = g_newre[((size_t)w * B_ + b) * R_ + lane];
    __syncwarp();

    const float* __restrict__ Wo = Wout + (size_t)w * D_ * R_;
    float* op = out + (size_t)b * D_;
    for (int d = lane; d < D_; d += 32) {
        const float4* wp = reinterpret_cast<const float4*>(Wo + (size_t)d * R_);
        float s = 0.f;
#pragma unroll
        for (int q = 0; q < 8; q++) {
            float4 wv = __ldg(wp + q);
            s = fmaf(nr_sh[wslot][4 * q + 0], wv.x, s);
            s = fmaf(nr_sh[wslot][4 * q + 1], wv.y, s);
            s = fmaf(nr_sh[wslot][4 * q + 2], wv.z, s);
            s = fmaf(nr_sh[wslot][4 * q + 3], wv.w, s);
        }
        op[d] = s;
    }
}

// ---------------------------------------------------------------------------
extern "C" void kernel_launch(void* const* d_in, const int* in_sizes, int n_in,
                              void* d_out, int out_size)
{
    const float* x    = (const float*)d_in[0];
    const float* sre  = (const float*)d_in[1];
    const float* sim  = (const float*)d_in[2];
    const float* A    = (const float*)d_in[3];
    const float* Win  = (const float*)d_in[4];
    const float* Wdt  = (const float*)d_in[5];
    const float* Wph  = (const float*)d_in[6];
    const float* Wout = (const float*)d_in[7];
    const float* lom  = (const float*)d_in[8];
    const float* ltm  = (const float*)d_in[9];
    const float* nuv  = (const float*)d_in[10];
    float* out = (float*)d_out;

    cudaFuncSetAttribute(km_mma, cudaFuncAttributeMaxDynamicSharedMemorySize, SM_TOT);
    cudaFuncSetAttribute(kg_mma, cudaFuncAttributeMaxDynamicSharedMemorySize, SM_TOT);

    k0a_split<<<(E_ * D_ * (D_ / 4) + 255) / 256, 256>>>(A);
    k0w_split<<<(E_ * 128 * (D_ / 4) + 255) / 256, 256>>>(Win, Wdt, Wph);
    km_mma<<<dim3(3, 8), NT_GEMM, SM_TOT>>>();
    k0x_split<<<(B_ * (D_ / 4) + 255) / 256, 256>>>(x);

    kg_mma<<<dim3(4, B_ / BM, E_), NT_GEMM, SM_TOT>>>(x, sre, sim, lom, ltm, nuv);

    k3_out<<<B_ / 4, 128>>>(Wout, out);
}

// round 14
// speedup vs baseline: 1.0019x; 1.0019x over previous
#include <cuda_runtime.h>
#include <cuda_bf16.h>
#include <math.h>
#include <stdint.h>

#define E_   8
#define B_   16384
#define D_   384
#define R_   32

#define BM 128
#define BN 128

// ---------------------------------------------------------------------------
// Static scratch (~77 MB total)
// ---------------------------------------------------------------------------
__device__ double                       g_err2[3 * E_ * B_];          // 3 MB
__device__ float                        g_newre[E_ * B_ * R_];        // 17 MB
__device__ __align__(16) __nv_bfloat16  g_xsp[3][B_ * D_];            // 37.7 MB (full B)
__device__ __align__(16) __nv_bfloat16  g_asp[3][E_ * D_ * D_];       // 7.1 MB ([e][f][d])
__device__ __align__(16) __nv_bfloat16  g_asp2[3][E_ * D_ * D_];      // 7.1 MB ([e][d][f])
__device__ __align__(16) __nv_bfloat16  g_wsp[3][E_ * 128 * D_];      // 2.4 MB ([e][n][f])
__device__ __align__(16) __nv_bfloat16  g_msp[3][E_ * 128 * D_];      // 2.4 MB (M^T: [e][n][d])

// ---------------------------------------------------------------------------
// k0a: split A_align into BOTH orientations (once).
// g_asp  [s][e][f][d]  (B-operand for x_al tiles)
// g_asp2 [s][e][d][f]  (B-operand for M = A @ Wc^T)
// ---------------------------------------------------------------------------
__global__ __launch_bounds__(256)
void k0a_split(const float* __restrict__ A)
{
    int idx = blockIdx.x * 256 + threadIdx.x;           // over E*384*96
    if (idx >= E_ * D_ * (D_ / 4)) return;
    int e  = idx / (D_ * (D_ / 4));
    int r  = idx % (D_ * (D_ / 4));
    int k  = r / (D_ / 4);                              // d index
    int n4 = (r % (D_ / 4)) * 4;                        // f index base
    float4 v = *reinterpret_cast<const float4*>(A + ((size_t)e * D_ + k) * D_ + n4);
    const float vv[4] = {v.x, v.y, v.z, v.w};
#pragma unroll
    for (int i = 0; i < 4; i++) {
        float f = vv[i];
        __nv_bfloat16 h1 = __float2bfloat16(f);
        float r1 = f - __bfloat162float(h1);
        __nv_bfloat16 h2 = __float2bfloat16(r1);
        float r2 = r1 - __bfloat162float(h2);
        __nv_bfloat16 h3 = __float2bfloat16(r2);
        size_t o1 = ((size_t)e * D_ + (n4 + i)) * D_ + k;   // [f][d]
        size_t o2 = ((size_t)e * D_ + k) * D_ + (n4 + i);   // [d][f]
        g_asp[0][o1] = h1; g_asp[1][o1] = h2; g_asp[2][o1] = h3;
        g_asp2[0][o2] = h1; g_asp2[1][o2] = h2; g_asp2[2][o2] = h3;
    }
}

// ---------------------------------------------------------------------------
// k0x: split x (full B) -> g_xsp[s][b][d] (bf16).
// ---------------------------------------------------------------------------
__global__ __launch_bounds__(256)
void k0x_split(const float* __restrict__ x)
{
    int idx = blockIdx.x * 256 + threadIdx.x;           // over B*96
    if (idx >= B_ * (D_ / 4)) return;
    int b  = idx / (D_ / 4);
    int k4 = (idx % (D_ / 4)) * 4;
    float4 v = *reinterpret_cast<const float4*>(x + (size_t)b * D_ + k4);
    const float vv[4] = {v.x, v.y, v.z, v.w};
    __nv_bfloat16 o1[4], o2[4], o3[4];
#pragma unroll
    for (int i = 0; i < 4; i++) {
        float f = vv[i];
        __nv_bfloat16 h1 = __float2bfloat16(f);
        float r1 = f - __bfloat162float(h1);
        __nv_bfloat16 h2 = __float2bfloat16(r1);
        float r2 = r1 - __bfloat162float(h2);
        o1[i] = h1; o2[i] = h2; o3[i] = __float2bfloat16(r2);
    }
    size_t o = (size_t)b * D_ + k4;
    *reinterpret_cast<uint64_t*>(&g_xsp[0][o]) = *reinterpret_cast<uint64_t*>(o1);
    *reinterpret_cast<uint64_t*>(&g_xsp[1][o]) = *reinterpret_cast<uint64_t*>(o2);
    *reinterpret_cast<uint64_t*>(&g_xsp[2][o]) = *reinterpret_cast<uint64_t*>(o3);
}

// ---------------------------------------------------------------------------
// k0w: split combined weight block [gate|x_val|dt|phase] -> g_wsp[s][e][n][f].
// ---------------------------------------------------------------------------
__global__ __launch_bounds__(256)
void k0w_split(const float* __restrict__ Win, const float* __restrict__ Wdt,
               const float* __restrict__ Wph)
{
    int idx = blockIdx.x * 256 + threadIdx.x;           // over E*128*96
    if (idx >= E_ * 128 * (D_ / 4)) return;
    int e  = idx / (128 * (D_ / 4));
    int r  = idx % (128 * (D_ / 4));
    int n  = r / (D_ / 4);
    int k4 = (r % (D_ / 4)) * 4;
    const float* src;
    if (n < 64)      src = Win + ((size_t)e * (4 * R_) + n) * D_;
    else if (n < 96) src = Wdt + ((size_t)e * R_ + (n - 64)) * D_;
    else             src = Wph + ((size_t)e * R_ + (n - 96)) * D_;
    float4 v = *reinterpret_cast<const float4*>(src + k4);
    const float vv[4] = {v.x, v.y, v.z, v.w};
#pragma unroll
    for (int i = 0; i < 4; i++) {
        float f = vv[i];
        __nv_bfloat16 h1 = __float2bfloat16(f);
        float r1 = f - __bfloat162float(h1);
        __nv_bfloat16 h2 = __float2bfloat16(r1);
        float r2 = r1 - __bfloat162float(h2);
        __nv_bfloat16 h3 = __float2bfloat16(r2);
        size_t o = ((size_t)e * 128 + n) * D_ + k4 + i;
        g_wsp[0][o] = h1; g_wsp[1][o] = h2; g_wsp[2][o] = h3;
    }
}

// ---------------------------------------------------------------------------
// mma.sync / ldmatrix / cp.async helpers (baseline PTX, no 'a' features)
// ---------------------------------------------------------------------------
__device__ __forceinline__ uint32_t smem_u32(const void* p) {
    uint32_t a;
    asm("{ .reg .u64 t; cvta.to.shared.u64 t, %1; cvt.u32.u64 %0, t; }" : "=r"(a) : "l"(p));
    return a;
}
__device__ __forceinline__ void ldsm_x4(uint32_t* r, uint32_t a) {
    asm volatile("ldmatrix.sync.aligned.m8n8.x4.shared.b16 {%0,%1,%2,%3}, [%4];"
                 : "=r"(r[0]), "=r"(r[1]), "=r"(r[2]), "=r"(r[3]) : "r"(a));
}
__device__ __forceinline__ void mma_bf16(float* c, const uint32_t* a, uint32_t b0, uint32_t b1) {
    asm volatile("mma.sync.aligned.m16n8k16.row.col.f32.bf16.bf16.f32 "
                 "{%0,%1,%2,%3}, {%4,%5,%6,%7}, {%8,%9}, {%0,%1,%2,%3};"
                 : "+f"(c[0]), "+f"(c[1]), "+f"(c[2]), "+f"(c[3])
                 : "r"(a[0]), "r"(a[1]), "r"(a[2]), "r"(a[3]), "r"(b0), "r"(b1));
}
__device__ __forceinline__ void cp_async16(uint32_t dst, const void* src) {
    asm volatile("cp.async.cg.shared.global [%0], [%1], 16;"
                 :: "r"(dst), "l"(__cvta_generic_to_global(src)) : "memory");
}
#define CP_COMMIT()  asm volatile("cp.async.commit_group;" ::: "memory")
#define CP_WAIT(n)   asm volatile("cp.async.wait_group %0;" :: "n"(n) : "memory")

#define KC       64
#define TILE_B2  16384                 // 128 rows * 128 bytes
#define STAGE_B  (6 * TILE_B2)         // 98304: [op(2)][split(3)] tiles
#define SM_PD    (2 * STAGE_B)         // 196608
#define SM_TOT   (SM_PD + 1024)        // 197632

#define NT_GEMM  512                   // 16 warps: 4 m-groups x 4 n-groups

__device__ __forceinline__ float softplus_f(float z) {
    return fmaxf(z, 0.f) + log1pf(expf(-fabsf(z)));
}

// Shared mainloop body (16-warp version, warp tile 32x32).
#define MAINLOOP_CHUNK(stage)                                                   \
    _Pragma("unroll")                                                           \
    for (int ks = 0; ks < 4; ks++) {                                            \
        const uint32_t kb = (uint32_t)(ks * 32);                                \
        uint32_t xf[3][2][4];                                                   \
        _Pragma("unroll")                                                       \
        for (int s = 0; s < 3; s++)                                             \
            _Pragma("unroll")                                                   \
            for (int mi = 0; mi < 2; mi++) {                                    \
                int r_ = xrow + mi * 16;                                        \
                ldsm_x4(xf[s][mi], (stage) + s * TILE_B2 + r_ * 128             \
                                  + ((kb + xk0) ^ (uint32_t)((r_ & 7) << 4)));  \
            }                                                                   \
        uint32_t bfb[2][2][4];                                                  \
        _Pragma("unroll")                                                       \
        for (int t = 0; t < 2; t++) {                                           \
            int r_ = brow + t * 16;                                             \
            ldsm_x4(bfb[0][t], (stage) + 3 * TILE_B2 + r_ * 128                 \
                              + ((kb + bk0) ^ (uint32_t)((r_ & 7) << 4)));      \
        }                                                                       \
        _Pragma("unroll")                                                       \
        for (int sa = 0; sa < 3; sa++) {                                        \
            const int cur = sa & 1;                                             \
            if (sa < 2) {                                                       \
                _Pragma("unroll")                                               \
                for (int t = 0; t < 2; t++) {                                   \
                    int r_ = brow + t * 16;                                     \
                    ldsm_x4(bfb[cur ^ 1][t],                                    \
                            (stage) + (4 + sa) * TILE_B2 + r_ * 128             \
                            + ((kb + bk0) ^ (uint32_t)((r_ & 7) << 4)));        \
                }                                                               \
            }                                                                   \
            const int nsx = (sa == 0) ? 3 : (sa == 1) ? 2 : 1;                  \
            _Pragma("unroll")                                                   \
            for (int sx = 0; sx < 3; sx++) {                                    \
                if (sx < nsx) {                                                 \
                    _Pragma("unroll")                                           \
                    for (int mi = 0; mi < 2; mi++)                              \
                        _Pragma("unroll")                                       \
                        for (int ni = 0; ni < 4; ni++)                          \
                            mma_bf16(acc[mi][ni], xf[sx][mi],                   \
                                     bfb[cur][ni >> 1][(ni & 1) * 2],           \
                                     bfb[cur][ni >> 1][(ni & 1) * 2 + 1]);      \
                }                                                               \
            }                                                                   \
        }                                                                       \
    }

// 3-way bf16 split of a float pair, stored to g_msp-style arrays.
__device__ __forceinline__ void split_store_pair(
    __nv_bfloat16* p0, __nv_bfloat16* p1, __nv_bfloat16* p2,
    size_t oi, float c0, float c1)
{
    __nv_bfloat16 a1 = __float2bfloat16(c0);
    float q0 = c0 - __bfloat162float(a1);
    __nv_bfloat16 a2 = __float2bfloat16(q0);
    q0 -= __bfloat162float(a2);
    __nv_bfloat16 a3 = __float2bfloat16(q0);
    __nv_bfloat16 b1 = __float2bfloat16(c1);
    float q1 = c1 - __bfloat162float(b1);
    __nv_bfloat16 b2 = __float2bfloat16(q1);
    q1 -= __bfloat162float(b2);
    __nv_bfloat16 b3 = __float2bfloat16(q1);
    __nv_bfloat162 p;
    p.x = a1; p.y = b1; *reinterpret_cast<__nv_bfloat162*>(p0 + oi) = p;
    p.x = a2; p.y = b2; *reinterpret_cast<__nv_bfloat162*>(p1 + oi) = p;
    p.x = a3; p.y = b3; *reinterpret_cast<__nv_bfloat162*>(p2 + oi) = p;
}

// ---------------------------------------------------------------------------
// kM: M^T[e][n][d] = Wc[e] @ A[e]  (rows n=128, cols d per tile, K=f=384),
// output split 3-way bf16 to g_msp. Grid (3, 8), 512 threads.
// ---------------------------------------------------------------------------
__global__ __launch_bounds__(NT_GEMM, 1)
void km_mma()
{
    extern __shared__ char smem[];
    const uint32_t sb = smem_u32(smem);
    const int tid = threadIdx.x;
    const int wid = tid >> 5;
    const int l   = tid & 31;

    const int dt = blockIdx.x;   // 0..2 (d tile)
    const int e  = blockIdx.y;   // 0..7

    const int warp_m = (wid & 3) * 32;
    const int warp_n = (wid >> 2) * 32;

    const int      xrow = warp_m + (l & 15);
    const uint32_t xk0  = (uint32_t)((l >> 4) * 16);
    const int      brow = warp_n + ((l >> 4) << 3) + (l & 7);
    const uint32_t bk0  = (uint32_t)(((l >> 3) & 1) * 16);

    float acc[2][4][4] = {};

    auto issue = [&](int c) {
        const int buf = c & 1;
        const int k0  = c * KC;
#pragma unroll
        for (int it = 0; it < 12; it++) {
            int lin  = tid + it * NT_GEMM;
            int tile = lin >> 10;
            int u    = lin & 1023;
            int m    = u >> 3;
            int kk8  = (u & 7) * 8;
            const __nv_bfloat16* src;
            if (tile < 3)
                src = &g_wsp[tile][((size_t)e * 128 + m) * D_ + k0 + kk8];
            else
                src = &g_asp2[tile - 3][((size_t)e * D_ + dt * 128 + m) * D_ + k0 + kk8];
            uint32_t boff = (uint32_t)(m * 128 + kk8 * 2);
            uint32_t dst  = sb + buf * STAGE_B + tile * TILE_B2
                          + (boff ^ ((boff >> 3) & 0x70));
            cp_async16(dst, src);
        }
        CP_COMMIT();
    };

    issue(0);
    for (int c = 0; c < 6; c++) {
        if (c < 5) { issue(c + 1); CP_WAIT(1); }
        else       { CP_WAIT(0); }
        __syncthreads();
        const uint32_t stage = sb + (uint32_t)((c & 1) * STAGE_B);
        MAINLOOP_CHUNK(stage)
        __syncthreads();
    }

    // epilogue: split-store M^T rows (n) x cols (d tile)
    const int cb = (l & 3) * 2;
#pragma unroll
    for (int mi = 0; mi < 2; mi++)
#pragma unroll
        for (int h = 0; h < 2; h++) {
            const int rl = warp_m + mi * 16 + (l >> 2) + h * 8;       // n
            const size_t base = ((size_t)e * 128 + rl) * D_ + dt * 128 + warp_n;
#pragma unroll
            for (int ni = 0; ni < 4; ni++)
                split_store_pair(g_msp[0], g_msp[1], g_msp[2],
                                 base + ni * 8 + cb,
                                 acc[mi][ni][h * 2], acc[mi][ni][h * 2 + 1]);
        }
}

// ---------------------------------------------------------------------------
// kG (grand GEMM): grid (4, B/128, 8), 512 threads.
//   nt<3 : x_al tile = x @ A[e]^T  -> fp64 err^2 partials only
//   nt==3: proj = x @ M[e]        -> transcendental epilogue -> g_newre
// ---------------------------------------------------------------------------
__global__ __launch_bounds__(NT_GEMM, 1)
void kg_mma(const float* __restrict__ x,
            const float* __restrict__ sre, const float* __restrict__ sim,
            const float* __restrict__ lom, const float* __restrict__ ltm,
            const float* __restrict__ nuv)
{
    extern __shared__ char smem[];
    __shared__ float ph_sh[R_], ex_sh[R_];
    const uint32_t sb = smem_u32(smem);
    const int tid = threadIdx.x;
    const int wid = tid >> 5;
    const int l   = tid & 31;

    const int nt = blockIdx.x;   // 0..2: err tiles; 3: proj tile
    const int bt = blockIdx.y;   // 0..127
    const int e  = blockIdx.z;   // 0..7

    double* pd = reinterpret_cast<double*>(smem + SM_PD);
    if (nt < 3) {
        if (tid < 128) pd[tid] = 0.0;
    } else {
        if (tid < R_) {
            ph_sh[tid] = expf(lom[e * R_ + tid]) / (expf(ltm[e * R_ + tid]) + 1e-6f);
            ex_sh[tid] = expf(nuv[e * R_ + tid]);
        }
    }

    const int warp_m = (wid & 3) * 32;
    const int warp_n = (wid >> 2) * 32;

    const int      xrow = warp_m + (l & 15);
    const uint32_t xk0  = (uint32_t)((l >> 4) * 16);
    const int      brow = warp_n + ((l >> 4) << 3) + (l & 7);
    const uint32_t bk0  = (uint32_t)(((l >> 3) & 1) * 16);

    float acc[2][4][4] = {};

    auto issue = [&](int c) {
        const int buf = c & 1;
        const int k0  = c * KC;
#pragma unroll
        for (int it = 0; it < 12; it++) {
            int lin  = tid + it * NT_GEMM;
            int tile = lin >> 10;
            int u    = lin & 1023;
            int m    = u >> 3;
            int kk8  = (u & 7) * 8;
            const __nv_bfloat16* src;
            if (tile < 3)
                src = &g_xsp[tile][((size_t)(bt * BM + m)) * D_ + k0 + kk8];
            else if (nt < 3)
                src = &g_asp[tile - 3][((size_t)e * D_ + (nt * BN + m)) * D_ + k0 + kk8];
            else
                src = &g_msp[tile - 3][((size_t)e * 128 + m) * D_ + k0 + kk8];
            uint32_t boff = (uint32_t)(m * 128 + kk8 * 2);
            uint32_t dst  = sb + buf * STAGE_B + tile * TILE_B2
                          + (boff ^ ((boff >> 3) & 0x70));
            cp_async16(dst, src);
        }
        CP_COMMIT();
    };

    issue(0);
    for (int c = 0; c < 6; c++) {
        if (c < 5) { issue(c + 1); CP_WAIT(1); }
        else       { CP_WAIT(0); }
        __syncthreads();
        const uint32_t stage = sb + (uint32_t)((c & 1) * STAGE_B);
        MAINLOOP_CHUNK(stage)
        __syncthreads();
    }

    const int cb = (l & 3) * 2;
    if (nt < 3) {
        // ---- err^2 epilogue (fp64 partials only; no x_al store) ----
        double es[2][2] = {{0.0, 0.0}, {0.0, 0.0}};
#pragma unroll
        for (int mi = 0; mi < 2; mi++)
#pragma unroll
            for (int h = 0; h < 2; h++) {
                const int rl   = warp_m + mi * 16 + (l >> 2) + h * 8;
                const int grow = bt * BM + rl;
                const float* xp = x + (size_t)grow * D_ + nt * BN + warp_n;
                double s = 0.0;
#pragma unroll
                for (int ni = 0; ni < 4; ni++) {
                    float2 xv = *reinterpret_cast<const float2*>(xp + ni * 8 + cb);
                    float d0 = xv.x - acc[mi][ni][h * 2 + 0];
                    float d1 = xv.y - acc[mi][ni][h * 2 + 1];
                    s += (double)d0 * d0 + (double)d1 * d1;
                }
                es[mi][h] = s;
            }
#pragma unroll
        for (int mi = 0; mi < 2; mi++)
#pragma unroll
            for (int h = 0; h < 2; h++) {
                double s = es[mi][h];
                s += __shfl_xor_sync(0xFFFFFFFFu, s, 1);
                s += __shfl_xor_sync(0xFFFFFFFFu, s, 2);
                if ((l & 3) == 0)
                    atomicAdd(&pd[warp_m + mi * 16 + (l >> 2) + h * 8], s);
            }
        __syncthreads();
        if (tid < 128)
            g_err2[(size_t)nt * (E_ * B_) + (size_t)e * B_ + (size_t)(bt * BM + tid)]
                = pd[tid];
    } else {
        // ---- proj epilogue: stage to smem, transcendentals -> g_newre ----
        float* S = reinterpret_cast<float*>(smem);
#pragma unroll
        for (int mi = 0; mi < 2; mi++)
#pragma unroll
            for (int h = 0; h < 2; h++) {
                const int rl = warp_m + mi * 16 + (l >> 2) + h * 8;
#pragma unroll
                for (int ni = 0; ni < 4; ni++)
                    *reinterpret_cast<float2*>(&S[rl * 132 + warp_n + ni * 8 + cb]) =
                        make_float2(acc[mi][ni][h * 2], acc[mi][ni][h * 2 + 1]);
            }
        __syncthreads();
        const int row = tid >> 2;
        const int rh  = (tid & 3) * 8;
        const int b   = bt * BM + row;
        const float* srp = sre + ((size_t)e * B_ + b) * R_ + rh;
        const float* sip = sim + ((size_t)e * B_ + b) * R_ + rh;
        float* nrp = g_newre + ((size_t)e * B_ + b) * R_ + rh;
        const float PIf = 3.14159265358979323846f;
#pragma unroll
        for (int j = 0; j < 8; j++) {
            const int r = rh + j;
            float gate = S[row * 132 + r];
            float xval = S[row * 132 + 32 + r];
            float dtp  = S[row * 132 + 64 + r];
            float phv  = S[row * 132 + 96 + r];
            float dtv   = softplus_f(dtp);
            float phase = tanhf(phv) * PIf;
            float angle = dtv * (ph_sh[r] + phase);
            float dec   = expf(-dtv * ex_sh[r]);
            float sv, cv;
            sincosf(angle, &sv, &cv);
            float sig = 1.f / (1.f + expf(-gate));
            nrp[j] = (srp[j] * cv - sip[j] * sv) * dec + sig * xval;
        }
    }
}

// ---------------------------------------------------------------------------
// K3: per-row winner (argmin err^2) + out = new_re @ W_out^T   (unchanged)
// ---------------------------------------------------------------------------
__global__ __launch_bounds__(128)
void k3_out(const float* __restrict__ Wout, float* __restrict__ out)
{
    const int gwarp = (blockIdx.x * blockDim.x + threadIdx.x) >> 5;
    const int lane = threadIdx.x & 31;
    if (gwarp >= B_) return;
    const int b = gwarp;

    double v = 1.0e300;
    if (lane < E_) {
        const size_t idx = (size_t)lane * B_ + b;
        v = g_err2[idx] + g_err2[(size_t)(E_ * B_) + idx] + g_err2[2 * (size_t)(E_ * B_) + idx];
    }
    int w = lane;
#pragma unroll
    for (int ofs = 1; ofs < 8; ofs <<= 1) {
        double ov = __shfl_xor_sync(0xFFFFFFFFu, v, ofs);
        int    ow = __shfl_xor_sync(0xFFFFFFFFu, w, ofs);
        if (ov < v || (ov == v && ow < w)) { v = ov; w = ow; }
    }
    w = __shfl_sync(0xFFFFFFFFu, w, 0);

    __shared__ float nr_sh[4][R_];
    const int wslot = threadIdx.x >> 5;
    nr_sh[wslot][lane] = g_newre[((size_t)w * B_ + b) * R_ + lane];
    __syncwarp();

    const float* __restrict__ Wo = Wout + (size_t)w * D_ * R_;
    float* op = out + (size_t)b * D_;
    for (int d = lane; d < D_; d += 32) {
        const float4* wp = reinterpret_cast<const float4*>(Wo + (size_t)d * R_);
        float s = 0.f;
#pragma unroll
        for (int q = 0; q < 8; q++) {
            float4 wv = __ldg(wp + q);
            s = fmaf(nr_sh[wslot][4 * q + 0], wv.x, s);
            s = fmaf(nr_sh[wslot][4 * q + 1], wv.y, s);
            s = fmaf(nr_sh[wslot][4 * q + 2], wv.z, s);
            s = fmaf(nr_sh[wslot][4 * q + 3], wv.w, s);
        }
        op[d] = s;
    }
}

// ---------------------------------------------------------------------------
extern "C" void kernel_launch(void* const* d_in, const int* in_sizes, int n_in,
                              void* d_out, int out_size)
{
    const float* x    = (const float*)d_in[0];
    const float* sre  = (const float*)d_in[1];
    const float* sim  = (const float*)d_in[2];
    const float* A    = (const float*)d_in[3];
    const float* Win  = (const float*)d_in[4];
    const float* Wdt  = (const float*)d_in[5];
    const float* Wph  = (const float*)d_in[6];
    const float* Wout = (const float*)d_in[7];
    const float* lom  = (const float*)d_in[8];
    const float* ltm  = (const float*)d_in[9];
    const float* nuv  = (const float*)d_in[10];
    float* out = (float*)d_out;

    cudaFuncSetAttribute(km_mma, cudaFuncAttributeMaxDynamicSharedMemorySize, SM_TOT);
    cudaFuncSetAttribute(kg_mma, cudaFuncAttributeMaxDynamicSharedMemorySize, SM_TOT);

    k0a_split<<<(E_ * D_ * (D_ / 4) + 255) / 256, 256>>>(A);
    k0w_split<<<(E_ * 128 * (D_ / 4) + 255) / 256, 256>>>(Win, Wdt, Wph);
    km_mma<<<dim3(3, 8), NT_GEMM, SM_TOT>>>();
    k0x_split<<<(B_ * (D_ / 4) + 255) / 256, 256>>>(x);

    kg_mma<<<dim3(4, B_ / BM, E_), NT_GEMM, SM_TOT>>>(x, sre, sim, lom, ltm, nuv);

    k3_out<<<B_ / 4, 128>>>(Wout, out);
}